// round 11
// baseline (speedup 1.0000x reference)
#include <cuda_runtime.h>
#include <math.h>

// Problem constants (fixed by reference setup_inputs)
#define NB    8        // batches
#define NPIX  65536    // pixels per batch (256*256, C=1)
#define KB    256      // bins; bins[k] == k exactly
#define EPS   1e-10
#define NBX   64       // blocks per batch; 512 total, all co-resident
#define NSTATS 16      // joint-stats blocks per batch (bx 0..15)
#define MARG_BX NSTATS // marginal block id (bx 16)
#define NFIN  (NSTATS + 1)   // blocks arriving at bar2 per batch

// Scratch (__device__ globals; zero-initialized at load; every run restores
// the all-zero invariant so CUDA-graph replays start clean).
__device__ float  g_joint[NB * KB * KB];  // per-batch joint weight sums
__device__ float  g_pdf1 [NB * KB];       // marginal weight sums (x1)
__device__ float  g_pdf2 [NB * KB];       // marginal weight sums (x2)
__device__ double g_SJ  [NB];             // sum of joint
__device__ double g_SLJ [NB];             // sum of J * log2(J)
__device__ double g_h1  [NB];             // marginal entropy 1
__device__ double g_h2  [NB];             // marginal entropy 2
__device__ unsigned int g_bar1[NB];       // per-batch barrier (accum->stats)
__device__ unsigned int g_bar2[NB];       // per-batch completion counter

// ---------------------------------------------------------------------------
// Per-pixel sparse KDE: sigma=0.1, bin spacing 1.0 -> nearest bin only.
// Second-nearest weight <= exp(-12.5)=3.7e-6 (expected ~1e-7/pixel): < 1e-6
// relative perturbation. ALL THREE scatter-adds go to L2 via REDG (no smem
// ATOMS): rebalances the scatter load off the SM atomic unit onto the 192
// L2 slices' atomic ALUs, which phase 1 leaves half-idle.
// ---------------------------------------------------------------------------
__device__ __forceinline__ void mi_pix(float a, float c,
                                       float* __restrict__ p1,
                                       float* __restrict__ p2,
                                       float* __restrict__ J) {
    float v1 = a * 255.0f;
    float v2 = c * 255.0f;
    int i1 = __float2int_rn(v1);
    int i2 = __float2int_rn(v2);
    float f1 = v1 - (float)i1;            // f in [-0.5, 0.5]
    float f2 = v2 - (float)i2;
    float w1 = __expf(-50.0f * f1 * f1);
    float w2 = __expf(-50.0f * f2 * f2);
    atomicAdd(&p1[i1], w1);               // REDG -> L2 (4096 addrs total)
    atomicAdd(&p2[i2], w2);               // REDG -> L2
    atomicAdd(&J[i1 * KB + i2], w1 * w2); // REDG -> L2 (512K addrs)
}

// ---------------------------------------------------------------------------
// Reductions
// ---------------------------------------------------------------------------
__device__ __forceinline__ float warp_reduce_f(float v) {
#pragma unroll
    for (int o = 16; o > 0; o >>= 1)
        v += __shfl_down_sync(0xffffffffu, v, o);
    return v;
}
__device__ __forceinline__ double warp_reduce_d(double v) {
#pragma unroll
    for (int o = 16; o > 0; o >>= 1)
        v += __shfl_down_sync(0xffffffffu, v, o);
    return v;
}
__device__ __forceinline__ double block_reduce_bcast(double v, double* sh8) {
    const int lane = threadIdx.x & 31;
    const int wid  = threadIdx.x >> 5;
    double w = warp_reduce_d(v);
    if (lane == 0) sh8[wid] = w;
    __syncthreads();
    return sh8[0] + sh8[1] + sh8[2] + sh8[3] + sh8[4] + sh8[5] + sh8[6] + sh8[7];
}

__device__ __forceinline__ void jacc(float v, float& s, float& sl) {
    if (v > 0.0f) { s += v; sl += v * __log2f(v); }
}

// ---------------------------------------------------------------------------
// Fused kernel (R9 structure, marginals moved to REDG).
// Grid (NBX, NB) = 512 blocks, all concurrently resident
// (__launch_bounds__(256,4): 4*148 = 592 >= 512) -> spins cannot deadlock.
//
// Per batch b:
//  Phase 1 (64 blocks): 1024 pixels each, float4 loads; 3 REDG per pixel,
//           ZERO smem work (no histogram init/flush/syncthreads).
//  bar1[b]: threadfence + arrive; bx > 16 exits.
//  Phase 2: bx 0..15: joint stats (4096 cells, 4 independent float4 loads)
//           + zero-restore. bx==16: marginal entropies from g_pdf*.
//  Phase 3: last of 17 (bar2[b]) combines into out[b], resets batch state.
// H12 identity: -sum p*log2(p+EPS) ~= log2(S')*(S/S') - (sum J log2 J)/S',
// S' = S + EPS (deviation < 1e-12 bits).
// ---------------------------------------------------------------------------
__global__ __launch_bounds__(256, 4)
void mi_fused_kernel(const float* __restrict__ x1,
                     const float* __restrict__ x2,
                     float* __restrict__ out) {
    const int b    = blockIdx.y;
    const int bx   = blockIdx.x;
    const int t    = threadIdx.x;
    const int lane = t & 31;
    const int wid  = t >> 5;

    __shared__ double sh8a[8];
    __shared__ double sh8b[8];
    __shared__ unsigned int lastFlag;

    float* __restrict__ J  = g_joint + (size_t)b * KB * KB;
    float* __restrict__ P1 = g_pdf1 + b * KB;
    float* __restrict__ P2 = g_pdf2 + b * KB;

    // ================= Phase 1: accumulation (no smem) =================
    {
        const float4* __restrict__ q1 =
            (const float4*)(x1 + (size_t)b * NPIX + bx * 1024);
        const float4* __restrict__ q2 =
            (const float4*)(x2 + (size_t)b * NPIX + bx * 1024);
        float4 a = q1[t];
        float4 c = q2[t];
        mi_pix(a.x, c.x, P1, P2, J);
        mi_pix(a.y, c.y, P1, P2, J);
        mi_pix(a.z, c.z, P1, P2, J);
        mi_pix(a.w, c.w, P1, P2, J);
    }

    // ================= bar1: arrive (and early-exit) =================
    __threadfence();                      // drain this thread's REDGs
    __syncthreads();
    if (bx > MARG_BX) {                   // 47 blocks/batch: arrive and die
        if (t == 0) atomicAdd(&g_bar1[b], 1u);
        return;
    }
    if (t == 0) {
        atomicAdd(&g_bar1[b], 1u);
        while (*(volatile unsigned int*)&g_bar1[b] < NBX)
            __nanosleep(32);
    }
    __syncthreads();

    // ================= Phase 2: statistics =================
    if (bx < NSTATS) {
        // Joint stats: 4096 cells = 4 independent float4 per thread (MLP=4).
        float4* __restrict__ J4 = (float4*)J + bx * 1024 + t;
        float4 v0 = J4[0];
        float4 v1 = J4[256];
        float4 v2 = J4[512];
        float4 v3 = J4[768];

        const float4 z4 = make_float4(0.f, 0.f, 0.f, 0.f);
        J4[0]   = z4;                     // restore zeros for next replay
        J4[256] = z4;
        J4[512] = z4;
        J4[768] = z4;

        float sa = 0.0f, sla = 0.0f, sb = 0.0f, slb = 0.0f;
        jacc(v0.x, sa, sla); jacc(v0.y, sb, slb);
        jacc(v0.z, sa, sla); jacc(v0.w, sb, slb);
        jacc(v1.x, sa, sla); jacc(v1.y, sb, slb);
        jacc(v1.z, sa, sla); jacc(v1.w, sb, slb);
        jacc(v2.x, sa, sla); jacc(v2.y, sb, slb);
        jacc(v2.z, sa, sla); jacc(v2.w, sb, slb);
        jacc(v3.x, sa, sla); jacc(v3.y, sb, slb);
        jacc(v3.z, sa, sla); jacc(v3.w, sb, slb);

        float ws  = warp_reduce_f(sa + sb);
        float wsl = warp_reduce_f(sla + slb);
        if (lane == 0) { sh8a[wid] = (double)ws; sh8b[wid] = (double)wsl; }
        __syncthreads();
        if (t == 0) {
            double bs  = sh8a[0]+sh8a[1]+sh8a[2]+sh8a[3]+sh8a[4]+sh8a[5]+sh8a[6]+sh8a[7];
            double bsl = sh8b[0]+sh8b[1]+sh8b[2]+sh8b[3]+sh8b[4]+sh8b[5]+sh8b[6]+sh8b[7];
            atomicAdd(&g_SJ[b],  bs);
            atomicAdd(&g_SLJ[b], bsl);
        }
    } else {
        // bx == MARG_BX: marginal entropies (double path: h1+h2-h12 cancels).
        const double invN = 1.0 / (double)NPIX;
        double m1 = (double)P1[t] * invN;
        double m2 = (double)P2[t] * invN;
        P1[t] = 0.0f;                     // restore zero for replay
        P2[t] = 0.0f;

        double sum1 = block_reduce_bcast(m1, sh8a);
        __syncthreads();
        double sum2 = block_reduce_bcast(m2, sh8a);
        __syncthreads();

        double p1 = m1 / (sum1 + EPS);
        double p2 = m2 / (sum2 + EPS);
        double e1 = p1 * (double)log2f((float)(p1 + EPS));
        double e2 = p2 * (double)log2f((float)(p2 + EPS));

        double h1 = block_reduce_bcast(e1, sh8a);
        __syncthreads();
        double h2 = block_reduce_bcast(e2, sh8a);
        if (t == 0) {
            atomicAdd(&g_h1[b], -h1);
            atomicAdd(&g_h2[b], -h2);
        }
    }

    // ================= Phase 3: per-batch finalize =================
    __syncthreads();
    if (t == 0) {
        __threadfence();                  // order this block's stat atomics
        unsigned int old = atomicAdd(&g_bar2[b], 1u);
        lastFlag = (old == NFIN - 1) ? 1u : 0u;
    }
    __syncthreads();

    if (lastFlag && t == 0) {
        double SJ  = atomicAdd(&g_SJ[b],  0.0);
        double SLJ = atomicAdd(&g_SLJ[b], 0.0);
        double h1  = atomicAdd(&g_h1[b],  0.0);
        double h2  = atomicAdd(&g_h2[b],  0.0);

        double Sp  = SJ + EPS;
        double h12 = (SJ / Sp) * log2(Sp) - SLJ / Sp;
        double mi  = h1 + h2 - h12;
        out[b] = (float)(2.0 * mi / (h1 + h2));   // NORMALIZE

        // reset this batch's state for the next graph replay
        g_SJ[b] = 0.0; g_SLJ[b] = 0.0; g_h1[b] = 0.0; g_h2[b] = 0.0;
        g_bar1[b] = 0u;
        g_bar2[b] = 0u;
    }
}

// ---------------------------------------------------------------------------
// Launch: ONE kernel.
// ---------------------------------------------------------------------------
extern "C" void kernel_launch(void* const* d_in, const int* in_sizes, int n_in,
                              void* d_out, int out_size) {
    (void)in_sizes; (void)n_in; (void)out_size;
    const float* x1 = (const float*)d_in[0];
    const float* x2 = (const float*)d_in[1];
    float* out = (float*)d_out;

    dim3 grid(NBX, NB);                   // (64, 8) = 512 blocks
    mi_fused_kernel<<<grid, 256>>>(x1, x2, out);
}

// round 12
// speedup vs baseline: 2.3796x; 2.3796x over previous
#include <cuda_runtime.h>
#include <math.h>

// Problem constants (fixed by reference setup_inputs)
#define NB    8        // batches
#define NPIX  65536    // pixels per batch (256*256, C=1)
#define KB    256      // bins; bins[k] == k exactly
#define EPS   1e-10
#define NBX   128      // blocks per batch; 1024 total
#define NT    128      // threads per block
#define NSHARD 8       // marginal flush shards (contention / 8)
#define NSTATS 16      // joint-stats blocks per batch (bx 0..15)
#define MARG_BX NSTATS // marginal block id (bx 16)
#define NFIN  (NSTATS + 1)   // blocks arriving at bar2 per batch

// Scratch (__device__ globals; zero-initialized at load; every run restores
// the all-zero invariant so CUDA-graph replays start clean).
__device__ float  g_joint[NB * KB * KB];        // per-batch joint sums
__device__ float  g_pdf1s[NB * NSHARD * KB];    // sharded marginal sums (x1)
__device__ float  g_pdf2s[NB * NSHARD * KB];    // sharded marginal sums (x2)
__device__ double g_SJ  [NB];                   // sum of joint
__device__ double g_SLJ [NB];                   // sum of J * log2(J)
__device__ double g_h1  [NB];                   // marginal entropy 1
__device__ double g_h2  [NB];                   // marginal entropy 2
__device__ unsigned int g_bar1[NB];             // per-batch barrier
__device__ unsigned int g_bar2[NB];             // per-batch completion counter

// ---------------------------------------------------------------------------
// Per-pixel sparse KDE: sigma=0.1, bin spacing 1.0 -> nearest bin only.
// Second-nearest weight <= exp(-12.5)=3.7e-6 (expected ~1e-7/pixel): < 1e-6
// relative perturbation. 2 exp2 + 2 smem ATOMS + 1 spread REDG per pixel.
// exp(-50 f^2) = 2^(-72.134752 f^2): folds the log2e multiply into the const.
// ---------------------------------------------------------------------------
__device__ __forceinline__ void mi_pix(float a, float c,
                                       float* __restrict__ s1,
                                       float* __restrict__ s2,
                                       float* __restrict__ J) {
    float v1 = a * 255.0f;
    float v2 = c * 255.0f;
    int i1 = __float2int_rn(v1);
    int i2 = __float2int_rn(v2);
    float f1 = v1 - (float)i1;            // f in [-0.5, 0.5]
    float f2 = v2 - (float)i2;
    float w1 = exp2f(-72.134752f * f1 * f1);
    float w2 = exp2f(-72.134752f * f2 * f2);
    atomicAdd(&s1[i1], w1);
    atomicAdd(&s2[i2], w2);
    atomicAdd(&J[i1 * KB + i2], w1 * w2);
}

// ---------------------------------------------------------------------------
// Reductions (128-thread blocks: 4 warps)
// ---------------------------------------------------------------------------
__device__ __forceinline__ float warp_reduce_f(float v) {
#pragma unroll
    for (int o = 16; o > 0; o >>= 1)
        v += __shfl_down_sync(0xffffffffu, v, o);
    return v;
}
__device__ __forceinline__ double warp_reduce_d(double v) {
#pragma unroll
    for (int o = 16; o > 0; o >>= 1)
        v += __shfl_down_sync(0xffffffffu, v, o);
    return v;
}
__device__ __forceinline__ double block_reduce_bcast(double v, double* sh4) {
    const int lane = threadIdx.x & 31;
    const int wid  = threadIdx.x >> 5;
    double w = warp_reduce_d(v);
    if (lane == 0) sh4[wid] = w;
    __syncthreads();
    return sh4[0] + sh4[1] + sh4[2] + sh4[3];
}

__device__ __forceinline__ void jacc(float v, float& s, float& sl) {
    if (v > 0.0f) { s += v; sl += v * __log2f(v); }
}

// ---------------------------------------------------------------------------
// Fused kernel, fine-grained phase 1.
// Grid (NBX, NB) = 1024 blocks of 128 threads; __launch_bounds__(128, 8)
// gives 8 CTA slots/SM * 148 = 1184 >= 1024 -> ALL blocks co-resident, so
// per-batch spin barriers cannot deadlock. Halved per-block work halves the
// phase-1 straggle spread the barrier has to absorb.
//
// Per batch b (128 blocks):
//  Phase 1: 512 pixels/block (one float4 per input per thread). Marginal
//           histograms flushed to shard (bx & 7): 16 adds/address max.
//  bar1[b]: threadfence + arrive; bx > 16 exits.
//  Phase 2: bx 0..15: joint stats (4096 cells = 8 independent float4 loads
//           per thread, MLP=8) + zero-restore. bx==16: marginal entropies
//           from the 8 shards (+ zero-restore).
//  Phase 3: last of 17 (bar2[b]) combines into out[b], resets batch state.
// H12 identity: -sum p*log2(p+EPS) ~= log2(S')*(S/S') - (sum J log2 J)/S',
// S' = S + EPS (deviation < 1e-12 bits).
// ---------------------------------------------------------------------------
__global__ __launch_bounds__(NT, 8)
void mi_fused_kernel(const float* __restrict__ x1,
                     const float* __restrict__ x2,
                     float* __restrict__ out) {
    const int b    = blockIdx.y;
    const int bx   = blockIdx.x;
    const int t    = threadIdx.x;
    const int lane = t & 31;
    const int wid  = t >> 5;

    __shared__ float s1[KB];
    __shared__ float s2[KB];
    __shared__ double sh4a[4];
    __shared__ double sh4b[4];
    __shared__ unsigned int lastFlag;

    float* __restrict__ J = g_joint + (size_t)b * KB * KB;

    // ================= Phase 1: accumulation =================
    s1[t] = 0.0f; s1[t + NT] = 0.0f;
    s2[t] = 0.0f; s2[t + NT] = 0.0f;
    __syncthreads();

    {
        const float4* __restrict__ q1 =
            (const float4*)(x1 + (size_t)b * NPIX + bx * 512);
        const float4* __restrict__ q2 =
            (const float4*)(x2 + (size_t)b * NPIX + bx * 512);
        float4 a = q1[t];
        float4 c = q2[t];
        mi_pix(a.x, c.x, s1, s2, J);
        mi_pix(a.y, c.y, s1, s2, J);
        mi_pix(a.z, c.z, s1, s2, J);
        mi_pix(a.w, c.w, s1, s2, J);
    }

    __syncthreads();
    {   // sharded flush: shard = bx & 7 -> at most 16 REDG per address
        float* __restrict__ P1 = g_pdf1s + ((b * NSHARD) + (bx & 7)) * KB;
        float* __restrict__ P2 = g_pdf2s + ((b * NSHARD) + (bx & 7)) * KB;
        atomicAdd(&P1[t],      s1[t]);
        atomicAdd(&P1[t + NT], s1[t + NT]);
        atomicAdd(&P2[t],      s2[t]);
        atomicAdd(&P2[t + NT], s2[t + NT]);
    }

    // ================= bar1: arrive (and early-exit) =================
    __threadfence();                      // drain this thread's atomics
    __syncthreads();
    if (bx > MARG_BX) {                   // 111 blocks/batch: arrive and die
        if (t == 0) atomicAdd(&g_bar1[b], 1u);
        return;
    }
    if (t == 0) {
        atomicAdd(&g_bar1[b], 1u);
        while (*(volatile unsigned int*)&g_bar1[b] < NBX)
            __nanosleep(32);
    }
    __syncthreads();

    // ================= Phase 2: statistics =================
    if (bx < NSTATS) {
        // Joint stats: 4096 cells = 8 independent float4 per thread (MLP=8).
        float4* __restrict__ J4 = (float4*)J + bx * 1024 + t;
        float4 v0 = J4[0];
        float4 v1 = J4[NT];
        float4 v2 = J4[2 * NT];
        float4 v3 = J4[3 * NT];
        float4 v4 = J4[4 * NT];
        float4 v5 = J4[5 * NT];
        float4 v6 = J4[6 * NT];
        float4 v7 = J4[7 * NT];

        const float4 z4 = make_float4(0.f, 0.f, 0.f, 0.f);
        J4[0]      = z4;                  // restore zeros for next replay
        J4[NT]     = z4;
        J4[2 * NT] = z4;
        J4[3 * NT] = z4;
        J4[4 * NT] = z4;
        J4[5 * NT] = z4;
        J4[6 * NT] = z4;
        J4[7 * NT] = z4;

        float sa = 0.0f, sla = 0.0f, sb = 0.0f, slb = 0.0f;
        jacc(v0.x, sa, sla); jacc(v0.y, sb, slb);
        jacc(v0.z, sa, sla); jacc(v0.w, sb, slb);
        jacc(v1.x, sa, sla); jacc(v1.y, sb, slb);
        jacc(v1.z, sa, sla); jacc(v1.w, sb, slb);
        jacc(v2.x, sa, sla); jacc(v2.y, sb, slb);
        jacc(v2.z, sa, sla); jacc(v2.w, sb, slb);
        jacc(v3.x, sa, sla); jacc(v3.y, sb, slb);
        jacc(v3.z, sa, sla); jacc(v3.w, sb, slb);
        jacc(v4.x, sa, sla); jacc(v4.y, sb, slb);
        jacc(v4.z, sa, sla); jacc(v4.w, sb, slb);
        jacc(v5.x, sa, sla); jacc(v5.y, sb, slb);
        jacc(v5.z, sa, sla); jacc(v5.w, sb, slb);
        jacc(v6.x, sa, sla); jacc(v6.y, sb, slb);
        jacc(v6.z, sa, sla); jacc(v6.w, sb, slb);
        jacc(v7.x, sa, sla); jacc(v7.y, sb, slb);
        jacc(v7.z, sa, sla); jacc(v7.w, sb, slb);

        float ws  = warp_reduce_f(sa + sb);
        float wsl = warp_reduce_f(sla + slb);
        if (lane == 0) { sh4a[wid] = (double)ws; sh4b[wid] = (double)wsl; }
        __syncthreads();
        if (t == 0) {
            atomicAdd(&g_SJ[b],  sh4a[0] + sh4a[1] + sh4a[2] + sh4a[3]);
            atomicAdd(&g_SLJ[b], sh4b[0] + sh4b[1] + sh4b[2] + sh4b[3]);
        }
    } else {
        // bx == MARG_BX: marginal entropies. Gather 8 shards per bin; each
        // thread owns bins t and t+128. Double path: h1+h2-h12 cancels.
        double m1a = 0.0, m1b = 0.0, m2a = 0.0, m2b = 0.0;
#pragma unroll
        for (int s = 0; s < NSHARD; ++s) {
            float* P1 = g_pdf1s + (b * NSHARD + s) * KB;
            float* P2 = g_pdf2s + (b * NSHARD + s) * KB;
            m1a += (double)P1[t];      m1b += (double)P1[t + NT];
            m2a += (double)P2[t];      m2b += (double)P2[t + NT];
            P1[t] = 0.0f; P1[t + NT] = 0.0f;   // restore zeros for replay
            P2[t] = 0.0f; P2[t + NT] = 0.0f;
        }
        const double invN = 1.0 / (double)NPIX;
        m1a *= invN; m1b *= invN; m2a *= invN; m2b *= invN;

        double sum1 = block_reduce_bcast(m1a + m1b, sh4a);
        __syncthreads();
        double sum2 = block_reduce_bcast(m2a + m2b, sh4a);
        __syncthreads();

        double r1 = 1.0 / (sum1 + EPS);
        double r2 = 1.0 / (sum2 + EPS);
        double p1a = m1a * r1, p1b = m1b * r1;
        double p2a = m2a * r2, p2b = m2b * r2;
        double e1 = p1a * (double)log2f((float)(p1a + EPS))
                  + p1b * (double)log2f((float)(p1b + EPS));
        double e2 = p2a * (double)log2f((float)(p2a + EPS))
                  + p2b * (double)log2f((float)(p2b + EPS));

        double h1 = block_reduce_bcast(e1, sh4a);
        __syncthreads();
        double h2 = block_reduce_bcast(e2, sh4a);
        if (t == 0) {
            atomicAdd(&g_h1[b], -h1);
            atomicAdd(&g_h2[b], -h2);
        }
    }

    // ================= Phase 3: per-batch finalize =================
    __syncthreads();
    if (t == 0) {
        __threadfence();                  // order this block's stat atomics
        unsigned int old = atomicAdd(&g_bar2[b], 1u);
        lastFlag = (old == NFIN - 1) ? 1u : 0u;
    }
    __syncthreads();

    if (lastFlag && t == 0) {
        double SJ  = atomicAdd(&g_SJ[b],  0.0);
        double SLJ = atomicAdd(&g_SLJ[b], 0.0);
        double h1  = atomicAdd(&g_h1[b],  0.0);
        double h2  = atomicAdd(&g_h2[b],  0.0);

        double Sp  = SJ + EPS;
        double h12 = (SJ / Sp) * log2(Sp) - SLJ / Sp;
        double mi  = h1 + h2 - h12;
        out[b] = (float)(2.0 * mi / (h1 + h2));   // NORMALIZE

        // reset this batch's state for the next graph replay
        g_SJ[b] = 0.0; g_SLJ[b] = 0.0; g_h1[b] = 0.0; g_h2[b] = 0.0;
        g_bar1[b] = 0u;
        g_bar2[b] = 0u;
    }
}

// ---------------------------------------------------------------------------
// Launch: ONE kernel, 1024 fine-grained blocks, all co-resident.
// ---------------------------------------------------------------------------
extern "C" void kernel_launch(void* const* d_in, const int* in_sizes, int n_in,
                              void* d_out, int out_size) {
    (void)in_sizes; (void)n_in; (void)out_size;
    const float* x1 = (const float*)d_in[0];
    const float* x2 = (const float*)d_in[1];
    float* out = (float*)d_out;

    dim3 grid(NBX, NB);                   // (128, 8) = 1024 blocks
    mi_fused_kernel<<<grid, NT>>>(x1, x2, out);
}